// round 6
// baseline (speedup 1.0000x reference)
#include <cuda_runtime.h>
#include <cstdint>

// GCNStage4_ReduceSum: out[t] += msg[e] for t = edge_index[1][e]
// msg: [NUM_EDGES, 32] f32; edge_index: [2, NUM_EDGES] int32 (harness); out: [num_nodes, 32] f32
//
// R6: scatter->gather. The fp32 atomic path is pinned at the L2 atomic-ALU
// ceiling (1.29 cyc/lane-op spread => ~47us for 12.8M v4 ops). Instead:
//   K_bin:    ELL-bin edge ids by target (int atomics only)
//   K_gather: one warp per node, sum messages with plain loads, single STG row
//   K_ovf:    degree>CAP spill handled by direct RED (probability ~0, correctness-safe)

#define FEAT 32
#define CAP 64
#define MAXN 100352          // >= num_nodes (100000), padded
#define OVF_CAP 8192

__device__ int g_cnt[MAXN];
__device__ int g_ell[(size_t)MAXN * CAP];   // 25.7 MB
__device__ int g_ovf_n;
__device__ int g_ovf[OVF_CAP];

__global__ void __launch_bounds__(256) bin_kernel(
        const int* __restrict__ tgt, int num_edges)
{
    int e = blockIdx.x * blockDim.x + threadIdx.x;
    if (e >= num_edges) return;
    int t = tgt[e];
    int pos = atomicAdd(&g_cnt[t], 1);
    if (pos < CAP) {
        g_ell[(size_t)t * CAP + pos] = e;
    } else {
        int p = atomicAdd(&g_ovf_n, 1);
        if (p < OVF_CAP) g_ovf[p] = e;
    }
}

__global__ void __launch_bounds__(256) gather_kernel(
        const float* __restrict__ msg,
        float* __restrict__ out,
        int num_nodes)
{
    int w    = (blockIdx.x * blockDim.x + threadIdx.x) >> 5;   // node id
    int lane = threadIdx.x & 31;                               // feature id
    if (w >= num_nodes) return;

    int deg = g_cnt[w];
    if (deg > CAP) deg = CAP;
    const int* ell = &g_ell[(size_t)w * CAP];

    float acc = 0.f;
    int j = 0;
    for (; j + 4 <= deg; j += 4) {
        int e0 = ell[j], e1 = ell[j + 1], e2 = ell[j + 2], e3 = ell[j + 3];
        float a = __ldcs(&msg[(size_t)e0 * FEAT + lane]);
        float b = __ldcs(&msg[(size_t)e1 * FEAT + lane]);
        float c = __ldcs(&msg[(size_t)e2 * FEAT + lane]);
        float d = __ldcs(&msg[(size_t)e3 * FEAT + lane]);
        acc += (a + b) + (c + d);
    }
    for (; j < deg; j++)
        acc += __ldcs(&msg[(size_t)ell[j] * FEAT + lane]);

    out[(size_t)w * FEAT + lane] = acc;
}

// Handles (vanishingly rare) degree-overflow edges: RED on top of gathered sums.
__global__ void __launch_bounds__(256) overflow_kernel(
        const float4* __restrict__ msg4,
        const int* __restrict__ tgt,
        float* __restrict__ out)
{
    int n = g_ovf_n;
    if (n > OVF_CAP) n = OVF_CAP;
    int i   = blockIdx.x * blockDim.x + threadIdx.x;
    int idx = i >> 3;
    int sub = i & 7;
    if (idx >= n) return;
    int e = g_ovf[idx];
    int t = tgt[e];
    float4 v = msg4[(size_t)e * 8 + sub];
    float* dst = out + (size_t)t * FEAT + sub * 4;
    asm volatile("red.global.add.v4.f32 [%0], {%1, %2, %3, %4};"
                 :: "l"(dst), "f"(v.x), "f"(v.y), "f"(v.z), "f"(v.w) : "memory");
}

// Fallback (unexpected num_nodes > MAXN): proven R5 atomic path.
__global__ void __launch_bounds__(256) scatter_fallback(
        const float4* __restrict__ msg4,
        const int* __restrict__ tgt,
        float* __restrict__ out,
        int num_frags)
{
    int id = blockIdx.x * blockDim.x + threadIdx.x;
    if (id >= num_frags) return;
    int e = id >> 3, sub = id & 7;
    int t = tgt[e];
    float4 v = __ldcs(&msg4[(size_t)e * 8 + sub]);
    float* dst = out + (size_t)t * FEAT + sub * 4;
    asm volatile("red.global.add.v4.f32 [%0], {%1, %2, %3, %4};"
                 :: "l"(dst), "f"(v.x), "f"(v.y), "f"(v.z), "f"(v.w) : "memory");
}

extern "C" void kernel_launch(void* const* d_in, const int* in_sizes, int n_in,
                              void* d_out, int out_size) {
    const float*  msg  = (const float*)d_in[0];
    const float4* msg4 = (const float4*)d_in[0];
    const int*    ei   = (const int*)d_in[1];   // int32 indices
    float*        out  = (float*)d_out;

    int num_edges = in_sizes[0] / FEAT;          // 1,600,000
    int num_nodes = out_size / FEAT;             // 100,000
    const int* tgt = ei + num_edges;             // row 1 of edge_index

    if (num_nodes > MAXN) {
        // Safety fallback: plain atomic scatter.
        cudaMemsetAsync(d_out, 0, (size_t)out_size * sizeof(float));
        int num_frags = num_edges * 8;
        scatter_fallback<<<(num_frags + 255) / 256, 256>>>(msg4, tgt, out, num_frags);
        return;
    }

    // 0) zero counters + overflow count (memset nodes are graph-capturable)
    void* cnt_ptr = nullptr;
    void* ovf_ptr = nullptr;
    cudaGetSymbolAddress(&cnt_ptr, g_cnt);
    cudaGetSymbolAddress(&ovf_ptr, g_ovf_n);
    cudaMemsetAsync(cnt_ptr, 0, (size_t)MAXN * sizeof(int));
    cudaMemsetAsync(ovf_ptr, 0, sizeof(int));

    // 1) bin edge ids by target node
    bin_kernel<<<(num_edges + 255) / 256, 256>>>(tgt, num_edges);

    // 2) gather: one warp per node, write each output row once
    int total_threads = num_nodes * 32;
    gather_kernel<<<(total_threads + 255) / 256, 256>>>(msg, out, num_nodes);

    // 3) overflow edges (normally zero) added atomically on top
    overflow_kernel<<<(OVF_CAP * 8) / 256, 256>>>(msg4, tgt, out);
}

// round 7
// speedup vs baseline: 1.8083x; 1.8083x over previous
#include <cuda_runtime.h>
#include <cstdint>

// GCNStage4_ReduceSum: out[t] += msg[e] for t = edge_index[1][e]
// msg: [NUM_EDGES, 32] f32; edge_index: [2, NUM_EDGES] int32 (harness); out: [num_nodes, 32] f32
//
// R7: back to the atomic scatter (R6 gather regressed: 86us vs 47.6us).
// Software-pipelined unroll-8: lanes 0..7 cover one edge row (RED.128 warp-op
// touches 4 cache lines only), 2-deep load pipeline keeps regs ~25 -> full
// occupancy, RED stream issued steadily between loads.

#define FEAT 32

__global__ void __launch_bounds__(256) scatter_add_main(
        const float4* __restrict__ msg4,
        const int* __restrict__ tgt,
        float* __restrict__ out)
{
    int tid  = threadIdx.x;
    int base = blockIdx.x * 2048 + tid;       // fragment id for u=0 (unroll 8, stride 256)
    int e0   = base >> 3;
    int sub  = tid & 7;                       // invariant across u
    int off  = sub * 4;

    const float4* src = msg4 + (size_t)e0 * 8 + sub;

    // 2-deep software pipeline: load(u+1) in flight while RED(u) issues
    int    t_cur = tgt[e0];
    float4 v_cur = __ldcs(src);

    #pragma unroll
    for (int u = 1; u < 8; u++) {
        int    t_nxt = tgt[e0 + 32 * u];
        float4 v_nxt = __ldcs(src + 256 * u);
        asm volatile("red.global.add.v4.f32 [%0], {%1, %2, %3, %4};"
                     :: "l"(out + (size_t)t_cur * FEAT + off),
                        "f"(v_cur.x), "f"(v_cur.y), "f"(v_cur.z), "f"(v_cur.w) : "memory");
        t_cur = t_nxt;
        v_cur = v_nxt;
    }
    asm volatile("red.global.add.v4.f32 [%0], {%1, %2, %3, %4};"
                 :: "l"(out + (size_t)t_cur * FEAT + off),
                    "f"(v_cur.x), "f"(v_cur.y), "f"(v_cur.z), "f"(v_cur.w) : "memory");
}

// Tail: one thread per remaining fragment (generic shapes).
__global__ void __launch_bounds__(256) scatter_add_tail(
        const float4* __restrict__ msg4,
        const int* __restrict__ tgt,
        float* __restrict__ out,
        int frag_start, int num_frags)
{
    int id = frag_start + blockIdx.x * blockDim.x + threadIdx.x;
    if (id >= num_frags) return;
    int e = id >> 3, sub = id & 7;
    int t = tgt[e];
    float4 v = __ldcs(&msg4[(size_t)e * 8 + sub]);
    float* dst = out + (size_t)t * FEAT + sub * 4;
    asm volatile("red.global.add.v4.f32 [%0], {%1, %2, %3, %4};"
                 :: "l"(dst), "f"(v.x), "f"(v.y), "f"(v.z), "f"(v.w) : "memory");
}

extern "C" void kernel_launch(void* const* d_in, const int* in_sizes, int n_in,
                              void* d_out, int out_size) {
    const float4* msg4 = (const float4*)d_in[0];
    const int*    ei   = (const int*)d_in[1];   // int32 indices
    float*        out  = (float*)d_out;

    int num_edges = in_sizes[0] / FEAT;          // 1,600,000
    const int* tgt = ei + num_edges;             // row 1 of edge_index

    // 1) zero the output (poisoned to 0xAA by harness); memset is capturable
    cudaMemsetAsync(d_out, 0, (size_t)out_size * sizeof(float));

    // 2) scatter-add: main kernel covers 2048 fragments per block, no guards
    int num_frags   = num_edges * 8;             // 12.8M
    int full_blocks = num_frags / 2048;          // 6250 exact here
    int rem_start   = full_blocks * 2048;
    if (full_blocks > 0)
        scatter_add_main<<<full_blocks, 256>>>(msg4, tgt, out);
    int rem = num_frags - rem_start;
    if (rem > 0)
        scatter_add_tail<<<(rem + 255) / 256, 256>>>(msg4, tgt, out, rem_start, num_frags);
}